// round 2
// baseline (speedup 1.0000x reference)
#include <cuda_runtime.h>
#include <cuda_bf16.h>

// Problem constants
#define VOCAB  32000
#define EMBED  100
#define E2     50      // EMBED/2 (packed pairs)
#define HID    128
#define BATCH  1024
#define SEQ    256

// -------- device scratch (no allocation allowed) --------
__device__ __align__(16) float g_P[VOCAB * HID];  // fused emb@W_ih^T + b_ih + b_hh (16.4 MB)
__device__ __align__(16) float g_H[BATCH * HID];  // h_last

// -------- packed f32x2 helpers --------
__device__ __forceinline__ unsigned long long ffma2(unsigned long long a,
                                                    unsigned long long b,
                                                    unsigned long long c) {
    unsigned long long d;
    asm("fma.rn.f32x2 %0, %1, %2, %3;" : "=l"(d) : "l"(a), "l"(b), "l"(c));
    return d;
}
__device__ __forceinline__ float2 unpack2(unsigned long long v) {
    float lo, hi;
    asm("mov.b64 {%0, %1}, %2;" : "=f"(lo), "=f"(hi) : "l"(v));
    return make_float2(lo, hi);
}

// ============================================================================
// Kernel A: P[v][j] = sum_e emb[v][e]*W_ih[j][e] + b_ih[j] + b_hh[j]
// 1000 blocks x 128 threads, 32 vocab rows per block, f32x2 over e-pairs.
// ============================================================================
__global__ void __launch_bounds__(128) k_precompute_P(
    const float* __restrict__ emb, const float* __restrict__ W_ih,
    const float* __restrict__ b_ih, const float* __restrict__ b_hh)
{
    extern __shared__ unsigned long long sm[];
    unsigned long long* Wt2 = sm;                 // [E2][HID] transposed, pair-packed
    unsigned long long* Et2 = sm + E2 * HID;      // [32][E2]  pair-packed
    const int tx = threadIdx.x;
    const int vbase = blockIdx.x * 32;

    // W_ih row-major [128,100] -> packed pairs, transposed into smem
    const unsigned long long* W2 = (const unsigned long long*)W_ih;
    for (int i = tx; i < HID * E2; i += 128) {
        int j = i / E2, e2 = i % E2;
        Wt2[e2 * HID + j] = W2[i];
    }
    // emb rows for this block (contiguous)
    const unsigned long long* Eg = (const unsigned long long*)emb;
    for (int i = tx; i < 32 * E2; i += 128)
        Et2[i] = Eg[(long long)vbase * E2 + i];
    __syncthreads();

    const float bias = b_ih[tx] + b_hh[tx];

    for (int vb = 0; vb < 32; vb += 8) {
        unsigned long long acc[8];
        #pragma unroll
        for (int v = 0; v < 8; v++) acc[v] = 0ULL;
        #pragma unroll
        for (int e2 = 0; e2 < E2; e2++) {
            unsigned long long w = Wt2[e2 * HID + tx];
            #pragma unroll
            for (int v = 0; v < 8; v++)
                acc[v] = ffma2(Et2[(vb + v) * E2 + e2], w, acc[v]);
        }
        #pragma unroll
        for (int v = 0; v < 8; v++) {
            float2 s = unpack2(acc[v]);
            g_P[(vbase + vb + v) * HID + tx] = s.x + s.y + bias;
        }
    }
}

// ============================================================================
// Kernel B: RNN scan. 256 blocks x 128 threads, 4 batch rows per block.
// W_hh row j lives in registers (64 packed pairs). h exchanged via smem
// double buffer; one __syncthreads per step. Token ids are INT32 (JAX
// downcasts int64 without x64 mode).
// ============================================================================
__global__ void __launch_bounds__(128, 2) k_rnn_scan(
    const int* __restrict__ x, const float* __restrict__ W_hh)
{
    __shared__ __align__(16) float hbuf[2][4][HID];
    const int j  = threadIdx.x;
    const int b0 = blockIdx.x * 4;

    // load W_hh row j as 64 packed pairs into registers
    unsigned long long wpk[64];
    const unsigned long long* Wr = (const unsigned long long*)W_hh + (long long)j * 64;
    #pragma unroll
    for (int q = 0; q < 64; q++) wpk[q] = Wr[q];

    #pragma unroll
    for (int r = 0; r < 4; r++) hbuf[0][r][j] = 0.0f;
    __syncthreads();

    int idxA[4];
    #pragma unroll
    for (int r = 0; r < 4; r++) idxA[r] = x[(b0 + r) * SEQ];

    int cur = 0;
    for (int t = 0; t < SEQ; t++) {
        // prefetch next step's token indices
        int idxB[4];
        if (t < SEQ - 1) {
            #pragma unroll
            for (int r = 0; r < 4; r++) idxB[r] = x[(b0 + r) * SEQ + t + 1];
        } else {
            #pragma unroll
            for (int r = 0; r < 4; r++) idxB[r] = idxA[r];
        }
        // P gather for THIS step — consumed only after the k-loop (latency hidden)
        float px[4];
        #pragma unroll
        for (int r = 0; r < 4; r++) px[r] = g_P[idxA[r] * HID + j];

        unsigned long long acc[4];
        #pragma unroll
        for (int r = 0; r < 4; r++) acc[r] = 0ULL;

        #pragma unroll
        for (int q = 0; q < 32; q++) {          // 4 k's per q
            #pragma unroll
            for (int r = 0; r < 4; r++) {
                ulonglong2 hv = ((const ulonglong2*)hbuf[cur][r])[q];  // broadcast LDS.128
                acc[r] = ffma2(hv.x, wpk[2 * q],     acc[r]);
                acc[r] = ffma2(hv.y, wpk[2 * q + 1], acc[r]);
            }
        }

        const int nxt = cur ^ 1;
        #pragma unroll
        for (int r = 0; r < 4; r++) {
            float2 s = unpack2(acc[r]);
            hbuf[nxt][r][j] = tanhf(s.x + s.y + px[r]);
        }
        #pragma unroll
        for (int r = 0; r < 4; r++) idxA[r] = idxB[r];
        cur = nxt;
        __syncthreads();
    }

    #pragma unroll
    for (int r = 0; r < 4; r++)
        g_H[(b0 + r) * HID + j] = hbuf[cur][r][j];
}

// ============================================================================
// Kernel C: out[b][v] = dot(h_last[b], W_fc[v]) + b_fc[v]
// 256 threads, 64b x 64v tile, 4x4 micro-tile, K=128 fully in smem.
// Rows padded to 132 floats (528 B, 16B-aligned) for conflict-free LDS.128.
// ============================================================================
#define CPAD 132
#define CPADQ 33   // CPAD floats = 33 ulonglong2

__global__ void __launch_bounds__(256) k_head(
    const float* __restrict__ W_fc, const float* __restrict__ b_fc,
    float* __restrict__ out)
{
    extern __shared__ float smf[];
    float* Hs = smf;                // [64][CPAD]
    float* Ws = smf + 64 * CPAD;    // [64][CPAD]
    const int tx = threadIdx.x;
    const int v0 = blockIdx.x * 64;
    const int b0 = blockIdx.y * 64;

    for (int i = tx; i < 64 * 32; i += 256) {   // 64 rows x 32 float4
        int row = i >> 5, k4 = i & 31;
        ((float4*)(Hs + row * CPAD))[k4] =
            ((const float4*)(g_H  + (b0 + row) * HID))[k4];
        ((float4*)(Ws + row * CPAD))[k4] =
            ((const float4*)(W_fc + (long long)(v0 + row) * HID))[k4];
    }
    __syncthreads();

    const int bi = tx >> 4;          // 0..15 -> b rows bi*4..bi*4+3
    const int vi = tx & 15;          // 0..15 -> v cols vi*4..vi*4+3
    const ulonglong2* hp = (const ulonglong2*)(Hs + bi * 4 * CPAD);
    const ulonglong2* wp = (const ulonglong2*)(Ws + vi * 4 * CPAD);

    unsigned long long acc[4][4];
    #pragma unroll
    for (int r = 0; r < 4; r++)
        #pragma unroll
        for (int c = 0; c < 4; c++) acc[r][c] = 0ULL;

    #pragma unroll
    for (int q = 0; q < 32; q++) {
        ulonglong2 h4[4], w4[4];
        #pragma unroll
        for (int r = 0; r < 4; r++) h4[r] = hp[r * CPADQ + q];
        #pragma unroll
        for (int c = 0; c < 4; c++) w4[c] = wp[c * CPADQ + q];
        #pragma unroll
        for (int r = 0; r < 4; r++)
            #pragma unroll
            for (int c = 0; c < 4; c++) {
                acc[r][c] = ffma2(h4[r].x, w4[c].x, acc[r][c]);
                acc[r][c] = ffma2(h4[r].y, w4[c].y, acc[r][c]);
            }
    }

    const int v = v0 + vi * 4;
    const float4 bfc = *(const float4*)(b_fc + v);
    #pragma unroll
    for (int r = 0; r < 4; r++) {
        const int b = b0 + bi * 4 + r;
        float2 s0 = unpack2(acc[r][0]);
        float2 s1 = unpack2(acc[r][1]);
        float2 s2 = unpack2(acc[r][2]);
        float2 s3 = unpack2(acc[r][3]);
        float4 o;
        o.x = s0.x + s0.y + bfc.x;
        o.y = s1.x + s1.y + bfc.y;
        o.z = s2.x + s2.y + bfc.z;
        o.w = s3.x + s3.y + bfc.w;
        *(float4*)(out + (long long)b * VOCAB + v) = o;
    }
}

// ============================================================================
// launch
// ============================================================================
extern "C" void kernel_launch(void* const* d_in, const int* in_sizes, int n_in,
                              void* d_out, int out_size) {
    const int*   x    = (const int*)d_in[0];     // int32: JAX downcasts int64
    const float* emb  = (const float*)d_in[1];
    const float* W_ih = (const float*)d_in[2];
    const float* W_hh = (const float*)d_in[3];
    const float* b_ih = (const float*)d_in[4];
    const float* b_hh = (const float*)d_in[5];
    const float* W_fc = (const float*)d_in[6];
    const float* b_fc = (const float*)d_in[7];
    float*       out  = (float*)d_out;

    // Kernel A: dynamic smem = Wt2 (50*128*8) + Et2 (32*50*8) = 64000 B
    const int smemA = (E2 * HID + 32 * E2) * 8;
    cudaFuncSetAttribute(k_precompute_P, cudaFuncAttributeMaxDynamicSharedMemorySize, smemA);
    // Kernel C: 2 * 64 * 132 * 4 = 67584 B
    const int smemC = 2 * 64 * CPAD * 4;
    cudaFuncSetAttribute(k_head, cudaFuncAttributeMaxDynamicSharedMemorySize, smemC);

    k_precompute_P<<<VOCAB / 32, 128, smemA>>>(emb, W_ih, b_ih, b_hh);
    k_rnn_scan<<<BATCH / 4, 128>>>(x, W_hh);
    dim3 gridC(VOCAB / 64, BATCH / 64);
    k_head<<<gridC, 256, smemC>>>(W_fc, b_fc, out);
}

// round 3
// speedup vs baseline: 1.5851x; 1.5851x over previous
#include <cuda_runtime.h>
#include <cuda_bf16.h>

// Problem constants
#define VOCAB  32000
#define EMBED  100
#define E2     50      // EMBED/2 (packed pairs)
#define E2P    25      // E2/2 (ulonglong2 quads)
#define HID    128
#define BATCH  1024
#define SEQ    256

// -------- device scratch (no allocation allowed) --------
__device__ __align__(16) float g_P[VOCAB * HID];  // fused emb@W_ih^T + b_ih + b_hh (16.4 MB)
__device__ __align__(16) float g_H[BATCH * HID];  // h_last

// -------- packed f32x2 helpers --------
__device__ __forceinline__ unsigned long long ffma2(unsigned long long a,
                                                    unsigned long long b,
                                                    unsigned long long c) {
    unsigned long long d;
    asm("fma.rn.f32x2 %0, %1, %2, %3;" : "=l"(d) : "l"(a), "l"(b), "l"(c));
    return d;
}
__device__ __forceinline__ float2 unpack2(unsigned long long v) {
    float lo, hi;
    asm("mov.b64 {%0, %1}, %2;" : "=f"(lo), "=f"(hi) : "l"(v));
    return make_float2(lo, hi);
}
// fast tanh: MUFU.EX2 based, ~1e-6 rel err, exact saturation at +-1
__device__ __forceinline__ float fast_tanh(float x) {
    float e = __expf(2.0f * x);
    return 1.0f - __fdividef(2.0f, e + 1.0f);
}

// ============================================================================
// Kernel A: P[v][j] = sum_e emb[v][e]*W_ih[j][e] + b_ih[j] + b_hh[j]
// 1000 blocks x 128 threads, 32 vocab rows per block. 16B smem loads on both
// operands: 9 LDS.128 per 16 FFMA2 (was 9 LDS.64 per 8).
// ============================================================================
__global__ void __launch_bounds__(128) k_precompute_P(
    const float* __restrict__ emb, const float* __restrict__ W_ih,
    const float* __restrict__ b_ih, const float* __restrict__ b_hh)
{
    extern __shared__ char smraw[];
    ulonglong2* Wp = (ulonglong2*)smraw;                              // [E2P][HID]
    unsigned long long* Et2 = (unsigned long long*)(smraw + E2P * HID * 16); // [32][E2]
    const int tx = threadIdx.x;
    const int vbase = blockIdx.x * 32;

    // W_ih row-major [128,100] -> quad-packed, transposed: Wp[p][j] = pairs (2p,2p+1) of row j
    const unsigned long long* W2 = (const unsigned long long*)W_ih;
    for (int i = tx; i < HID * E2P; i += 128) {
        int j = i / E2P, p = i % E2P;
        ulonglong2 v;
        v.x = W2[j * E2 + 2 * p];
        v.y = W2[j * E2 + 2 * p + 1];
        Wp[p * HID + j] = v;
    }
    // emb rows for this block (contiguous)
    const unsigned long long* Eg = (const unsigned long long*)emb;
    for (int i = tx; i < 32 * E2; i += 128)
        Et2[i] = Eg[(long long)vbase * E2 + i];
    __syncthreads();

    const float bias = b_ih[tx] + b_hh[tx];

    for (int vb = 0; vb < 32; vb += 8) {
        unsigned long long acc[8];
        #pragma unroll
        for (int v = 0; v < 8; v++) acc[v] = 0ULL;
        #pragma unroll
        for (int p = 0; p < E2P; p++) {
            ulonglong2 wv = Wp[p * HID + tx];          // conflict-free LDS.128
            #pragma unroll
            for (int v = 0; v < 8; v++) {
                ulonglong2 ev = ((const ulonglong2*)(Et2 + (vb + v) * E2))[p]; // broadcast
                acc[v] = ffma2(ev.x, wv.x, acc[v]);
                acc[v] = ffma2(ev.y, wv.y, acc[v]);
            }
        }
        #pragma unroll
        for (int v = 0; v < 8; v++) {
            float2 s = unpack2(acc[v]);
            g_P[(vbase + vb + v) * HID + tx] = s.x + s.y + bias;
        }
    }
}

// ============================================================================
// Kernel B: RNN scan. 256 blocks x 128 threads, 4 batch rows per block.
// W_hh row j lives in registers (64 packed pairs). h exchanged via smem
// double buffer; one __syncthreads per step. Token ids are INT32.
// ============================================================================
__global__ void __launch_bounds__(128, 2) k_rnn_scan(
    const int* __restrict__ x, const float* __restrict__ W_hh)
{
    __shared__ __align__(16) float hbuf[2][4][HID];
    const int j  = threadIdx.x;
    const int b0 = blockIdx.x * 4;

    // load W_hh row j as 64 packed pairs into registers
    unsigned long long wpk[64];
    const unsigned long long* Wr = (const unsigned long long*)W_hh + (long long)j * 64;
    #pragma unroll
    for (int q = 0; q < 64; q++) wpk[q] = Wr[q];

    #pragma unroll
    for (int r = 0; r < 4; r++) hbuf[0][r][j] = 0.0f;
    __syncthreads();

    int idxA[4];
    #pragma unroll
    for (int r = 0; r < 4; r++) idxA[r] = x[(b0 + r) * SEQ];

    int cur = 0;
    for (int t = 0; t < SEQ; t++) {
        // prefetch next step's token indices
        int idxB[4];
        if (t < SEQ - 1) {
            #pragma unroll
            for (int r = 0; r < 4; r++) idxB[r] = x[(b0 + r) * SEQ + t + 1];
        } else {
            #pragma unroll
            for (int r = 0; r < 4; r++) idxB[r] = idxA[r];
        }
        // P gather for THIS step — consumed only after the k-loop (latency hidden)
        float px[4];
        #pragma unroll
        for (int r = 0; r < 4; r++) px[r] = g_P[idxA[r] * HID + j];

        unsigned long long acc[4];
        #pragma unroll
        for (int r = 0; r < 4; r++) acc[r] = 0ULL;

        #pragma unroll
        for (int q = 0; q < 32; q++) {          // 4 k's per q
            #pragma unroll
            for (int r = 0; r < 4; r++) {
                ulonglong2 hv = ((const ulonglong2*)hbuf[cur][r])[q];  // broadcast LDS.128
                acc[r] = ffma2(hv.x, wpk[2 * q],     acc[r]);
                acc[r] = ffma2(hv.y, wpk[2 * q + 1], acc[r]);
            }
        }

        const int nxt = cur ^ 1;
        #pragma unroll
        for (int r = 0; r < 4; r++) {
            float2 s = unpack2(acc[r]);
            hbuf[nxt][r][j] = fast_tanh(s.x + s.y + px[r]);
        }
        #pragma unroll
        for (int r = 0; r < 4; r++) idxA[r] = idxB[r];
        cur = nxt;
        __syncthreads();
    }

    #pragma unroll
    for (int r = 0; r < 4; r++)
        g_H[(b0 + r) * HID + j] = hbuf[cur][r][j];
}

// ============================================================================
// Kernel C: out[b][v] = dot(h_last[b], W_fc[v]) + b_fc[v]
// 256 threads, 64b x 64v tile, 4x4 micro-tile, K=128 in smem.
// XOR swizzle on the 16B unit index (k4 ^ (row>>2)&7) makes every 8-lane
// LDS.128 phase conflict-free (row-major padding cannot: stride = 0/16 mod 32).
// ============================================================================
#define KQ 32   // 16B units per 128-float row

__global__ void __launch_bounds__(256) k_head(
    const float* __restrict__ W_fc, const float* __restrict__ b_fc,
    float* __restrict__ out)
{
    extern __shared__ float smf[];
    float4* Hs = (float4*)smf;            // [64][KQ]
    float4* Ws = ((float4*)smf) + 64 * KQ; // [64][KQ]
    const int tx = threadIdx.x;
    const int v0 = blockIdx.x * 64;
    const int b0 = blockIdx.y * 64;

    for (int i = tx; i < 64 * KQ; i += 256) {   // 64 rows x 32 float4
        int row = i >> 5, k4 = i & 31;
        int sw = k4 ^ ((row >> 2) & 7);
        Hs[row * KQ + sw] = ((const float4*)(g_H  + (b0 + row) * HID))[k4];
        Ws[row * KQ + sw] = ((const float4*)(W_fc + (long long)(v0 + row) * HID))[k4];
    }
    __syncthreads();

    const int bi = tx >> 4;          // 0..15 -> b rows bi*4..bi*4+3
    const int vi = tx & 15;          // 0..15 -> v cols vi*4..vi*4+3
    const int hsw = bi & 7;
    const int wsw = vi & 7;
    const ulonglong2* hp = (const ulonglong2*)Hs + bi * 4 * KQ;
    const ulonglong2* wp = (const ulonglong2*)Ws + vi * 4 * KQ;

    unsigned long long acc[4][4];
    #pragma unroll
    for (int r = 0; r < 4; r++)
        #pragma unroll
        for (int c = 0; c < 4; c++) acc[r][c] = 0ULL;

    #pragma unroll
    for (int q = 0; q < KQ; q++) {
        ulonglong2 h4[4], w4[4];
        const int hq = q ^ hsw, wq = q ^ wsw;
        #pragma unroll
        for (int r = 0; r < 4; r++) h4[r] = hp[r * KQ + hq];
        #pragma unroll
        for (int c = 0; c < 4; c++) w4[c] = wp[c * KQ + wq];
        #pragma unroll
        for (int r = 0; r < 4; r++)
            #pragma unroll
            for (int c = 0; c < 4; c++) {
                acc[r][c] = ffma2(h4[r].x, w4[c].x, acc[r][c]);
                acc[r][c] = ffma2(h4[r].y, w4[c].y, acc[r][c]);
            }
    }

    const int v = v0 + vi * 4;
    const float4 bfc = *(const float4*)(b_fc + v);
    #pragma unroll
    for (int r = 0; r < 4; r++) {
        const int b = b0 + bi * 4 + r;
        float2 s0 = unpack2(acc[r][0]);
        float2 s1 = unpack2(acc[r][1]);
        float2 s2 = unpack2(acc[r][2]);
        float2 s3 = unpack2(acc[r][3]);
        float4 o;
        o.x = s0.x + s0.y + bfc.x;
        o.y = s1.x + s1.y + bfc.y;
        o.z = s2.x + s2.y + bfc.z;
        o.w = s3.x + s3.y + bfc.w;
        *(float4*)(out + (long long)b * VOCAB + v) = o;
    }
}

// ============================================================================
// launch
// ============================================================================
extern "C" void kernel_launch(void* const* d_in, const int* in_sizes, int n_in,
                              void* d_out, int out_size) {
    const int*   x    = (const int*)d_in[0];     // int32: JAX downcasts int64
    const float* emb  = (const float*)d_in[1];
    const float* W_ih = (const float*)d_in[2];
    const float* W_hh = (const float*)d_in[3];
    const float* b_ih = (const float*)d_in[4];
    const float* b_hh = (const float*)d_in[5];
    const float* W_fc = (const float*)d_in[6];
    const float* b_fc = (const float*)d_in[7];
    float*       out  = (float*)d_out;

    // Kernel A: dynamic smem = Wp (25*128*16) + Et2 (32*50*8) = 64000 B
    const int smemA = E2P * HID * 16 + 32 * E2 * 8;
    cudaFuncSetAttribute(k_precompute_P, cudaFuncAttributeMaxDynamicSharedMemorySize, smemA);
    // Kernel C: 2 * 64 * 128 * 4 = 65536 B
    const int smemC = 2 * 64 * KQ * 16;
    cudaFuncSetAttribute(k_head, cudaFuncAttributeMaxDynamicSharedMemorySize, smemC);

    k_precompute_P<<<VOCAB / 32, 128, smemA>>>(emb, W_ih, b_ih, b_hh);
    k_rnn_scan<<<BATCH / 4, 128>>>(x, W_hh);
    dim3 gridC(VOCAB / 64, BATCH / 64);
    k_head<<<gridC, 256, smemC>>>(W_fc, b_fc, out);
}

// round 5
// speedup vs baseline: 1.7495x; 1.1037x over previous
#include <cuda_runtime.h>
#include <cuda_bf16.h>
#include <cstdint>

// Problem constants
#define VOCAB  32000
#define EMBED  100
#define HID    128
#define BATCH  1024
#define SEQ    256

// -------- device scratch (no allocation allowed) --------
__device__ __align__(16) float g_P[VOCAB * HID];  // fused emb@W_ih^T + b_ih + b_hh (16.4 MB)
__device__ __align__(16) float g_H[BATCH * HID];  // h_last

// ============================================================================
// mma.sync bf16 GEMM machinery (plain PTX ISA, works on base sm_100 target —
// tcgen05 is unavailable: harness compiles without the 'a' arch suffix).
// Split precision: x = hi(bf16) + lo(bf16); D = Ahi*Bhi + Ahi*Blo + Alo*Bhi
// with fp32 accumulation (~2^-18 operand error).
// ============================================================================
__device__ __forceinline__ uint32_t smem_u32(const void* p) {
    uint32_t a;
    asm("{ .reg .u64 t; cvta.to.shared.u64 t, %1; cvt.u32.u64 %0, t; }" : "=r"(a) : "l"(p));
    return a;
}
__device__ __forceinline__ void ldmx4(uint32_t* r, uint32_t a) {
    asm volatile("ldmatrix.sync.aligned.m8n8.x4.shared.b16 {%0,%1,%2,%3}, [%4];"
                 : "=r"(r[0]), "=r"(r[1]), "=r"(r[2]), "=r"(r[3]) : "r"(a));
}
__device__ __forceinline__ void mma_bf16(float* c, const uint32_t* a,
                                         uint32_t b0, uint32_t b1) {
    asm volatile("mma.sync.aligned.m16n8k16.row.col.f32.bf16.bf16.f32 "
                 "{%0,%1,%2,%3}, {%4,%5,%6,%7}, {%8,%9}, {%0,%1,%2,%3};"
                 : "+f"(c[0]), "+f"(c[1]), "+f"(c[2]), "+f"(c[3])
                 : "r"(a[0]), "r"(a[1]), "r"(a[2]), "r"(a[3]), "r"(b0), "r"(b1));
}

// Tiles: [128 rows][128 bf16 cols] = 16 units of 16B per row, XOR-swizzled:
// unit' = unit ^ (row & 7). Row stride 256B.
#define TILE_B 32768
__device__ __forceinline__ uint32_t tswz(int row, int u) {
    return (uint32_t)(row * 256 + ((u ^ (row & 7)) << 4));
}

// Convert fp32 [rows][ld] tile (Kvalid cols, zero-pad to 128) into hi/lo bf16
__device__ __forceinline__ void cvt_tile(const float* __restrict__ src, int ld,
                                         int Kv, char* hi, char* lo, int tid) {
    for (int i = tid; i < 128 * 16; i += 256) {
        int row = i >> 4, u = i & 15, c0 = u * 8;
        float v[8] = {0, 0, 0, 0, 0, 0, 0, 0};
        if (c0 + 8 <= Kv) {
            float4 a = *(const float4*)(src + (long long)row * ld + c0);
            float4 b = *(const float4*)(src + (long long)row * ld + c0 + 4);
            v[0]=a.x; v[1]=a.y; v[2]=a.z; v[3]=a.w; v[4]=b.x; v[5]=b.y; v[6]=b.z; v[7]=b.w;
        } else if (c0 < Kv) {
            #pragma unroll
            for (int t = 0; t < 8; t++) if (c0 + t < Kv) v[t] = src[(long long)row * ld + c0 + t];
        }
        uint32_t ph[4], pl[4];
        #pragma unroll
        for (int q = 0; q < 4; q++) {
            float a = v[2 * q], b = v[2 * q + 1];
            __nv_bfloat16 ha = __float2bfloat16_rn(a), hb = __float2bfloat16_rn(b);
            __nv_bfloat16 la = __float2bfloat16_rn(a - __bfloat162float(ha));
            __nv_bfloat16 lb = __float2bfloat16_rn(b - __bfloat162float(hb));
            ph[q] = (uint32_t)*(uint16_t*)&ha | ((uint32_t)*(uint16_t*)&hb << 16);
            pl[q] = (uint32_t)*(uint16_t*)&la | ((uint32_t)*(uint16_t*)&lb << 16);
        }
        uint32_t off = tswz(row, u);
        *(uint4*)(hi + off) = make_uint4(ph[0], ph[1], ph[2], ph[3]);
        *(uint4*)(lo + off) = make_uint4(pl[0], pl[1], pl[2], pl[3]);
    }
}

// Unified GEMM: out[m0+i][n0+j] = sum_k A[m0+i][k]*B[n0+j][k] + bias[n0+j]
// Block tile 128x128, K=128 (padded). 8 warps x (16 M-rows, full N=128).
__global__ void __launch_bounds__(256) k_gemm_mma(
    const float* __restrict__ A, int lda,
    const float* __restrict__ B, int ldb, int Kvalid,
    float* __restrict__ out, long long ldout,
    const float* __restrict__ bias1, const float* __restrict__ bias2)
{
    extern __shared__ __align__(16) char sm[];
    __shared__ float sbias[128];
    char* Ahi = sm;
    char* Alo = sm + TILE_B;
    char* Bhi = sm + 2 * TILE_B;
    char* Blo = sm + 3 * TILE_B;

    const int tid = threadIdx.x, w = tid >> 5, lane = tid & 31;
    const int m0 = blockIdx.x * 128, n0 = blockIdx.y * 128;

    cvt_tile(A + (long long)m0 * lda, lda, Kvalid, Ahi, Alo, tid);
    cvt_tile(B + (long long)n0 * ldb, ldb, Kvalid, Bhi, Blo, tid);
    if (tid < 128) sbias[tid] = bias1[n0 + tid] + (bias2 ? bias2[n0 + tid] : 0.0f);
    __syncthreads();

    // ldmatrix lane addressing (swizzle selector = lane&7 for both operands)
    const int sw = lane & 7;
    const int arow = w * 16 + (lane & 7) + 8 * ((lane >> 3) & 1);
    const int akh  = lane >> 4;
    const int brloc = (lane & 7) + 8 * (lane >> 4);
    const int bkh  = (lane >> 3) & 1;

    const uint32_t sAhi = smem_u32(Ahi) + arow * 256;
    const uint32_t sAlo = smem_u32(Alo) + arow * 256;
    const uint32_t sBhi = smem_u32(Bhi) + brloc * 256;
    const uint32_t sBlo = smem_u32(Blo) + brloc * 256;

    float acc[16][4];
    #pragma unroll
    for (int nt = 0; nt < 16; nt++)
        #pragma unroll
        for (int q = 0; q < 4; q++) acc[nt][q] = 0.0f;

    #pragma unroll
    for (int ks = 0; ks < 8; ks++) {
        const uint32_t uA = ((2 * ks + akh) ^ sw) << 4;
        const uint32_t uB = ((2 * ks + bkh) ^ sw) << 4;
        uint32_t aHi[4], aLo[4];
        ldmx4(aHi, sAhi + uA);
        ldmx4(aLo, sAlo + uA);
        #pragma unroll
        for (int np = 0; np < 8; np++) {
            uint32_t bh[4];
            ldmx4(bh, sBhi + np * 16 * 256 + uB);
            mma_bf16(acc[2 * np],     aHi, bh[0], bh[1]);
            mma_bf16(acc[2 * np + 1], aHi, bh[2], bh[3]);
            mma_bf16(acc[2 * np],     aLo, bh[0], bh[1]);
            mma_bf16(acc[2 * np + 1], aLo, bh[2], bh[3]);
        }
        #pragma unroll
        for (int np = 0; np < 8; np++) {
            uint32_t bl[4];
            ldmx4(bl, sBlo + np * 16 * 256 + uB);
            mma_bf16(acc[2 * np],     aHi, bl[0], bl[1]);
            mma_bf16(acc[2 * np + 1], aHi, bl[2], bl[3]);
        }
    }

    // epilogue: acc rows = M (m0 + w*16 + g [+8]), cols = N (nt*8 + 2*tig [+1])
    const int g = lane >> 2, tig = lane & 3;
    const long long r0 = (long long)(m0 + w * 16 + g) * ldout + n0;
    const long long r1 = r0 + 8 * ldout;
    #pragma unroll
    for (int nt = 0; nt < 16; nt++) {
        const int col = nt * 8 + 2 * tig;
        const float bx = sbias[col], by = sbias[col + 1];
        *(float2*)(out + r0 + col) = make_float2(acc[nt][0] + bx, acc[nt][1] + by);
        *(float2*)(out + r1 + col) = make_float2(acc[nt][2] + bx, acc[nt][3] + by);
    }
}

// ============================================================================
// Kernel B: RNN scan (unchanged — near fp32 FFMA2 chip floor).
// ============================================================================
__device__ __forceinline__ unsigned long long ffma2(unsigned long long a,
                                                    unsigned long long b,
                                                    unsigned long long c) {
    unsigned long long d;
    asm("fma.rn.f32x2 %0, %1, %2, %3;" : "=l"(d) : "l"(a), "l"(b), "l"(c));
    return d;
}
__device__ __forceinline__ float2 unpack2(unsigned long long v) {
    float lo, hi;
    asm("mov.b64 {%0, %1}, %2;" : "=f"(lo), "=f"(hi) : "l"(v));
    return make_float2(lo, hi);
}
__device__ __forceinline__ float fast_tanh(float x) {
    float e = __expf(2.0f * x);
    return 1.0f - __fdividef(2.0f, e + 1.0f);
}

__global__ void __launch_bounds__(128, 2) k_rnn_scan(
    const int* __restrict__ x, const float* __restrict__ W_hh)
{
    __shared__ __align__(16) float hbuf[2][4][HID];
    const int j  = threadIdx.x;
    const int b0 = blockIdx.x * 4;

    unsigned long long wpk[64];
    const unsigned long long* Wr = (const unsigned long long*)W_hh + (long long)j * 64;
    #pragma unroll
    for (int q = 0; q < 64; q++) wpk[q] = Wr[q];

    #pragma unroll
    for (int r = 0; r < 4; r++) hbuf[0][r][j] = 0.0f;
    __syncthreads();

    int idxA[4];
    #pragma unroll
    for (int r = 0; r < 4; r++) idxA[r] = x[(b0 + r) * SEQ];

    int cur = 0;
    for (int t = 0; t < SEQ; t++) {
        int idxB[4];
        if (t < SEQ - 1) {
            #pragma unroll
            for (int r = 0; r < 4; r++) idxB[r] = x[(b0 + r) * SEQ + t + 1];
        } else {
            #pragma unroll
            for (int r = 0; r < 4; r++) idxB[r] = idxA[r];
        }
        float px[4];
        #pragma unroll
        for (int r = 0; r < 4; r++) px[r] = g_P[idxA[r] * HID + j];

        unsigned long long acc[4];
        #pragma unroll
        for (int r = 0; r < 4; r++) acc[r] = 0ULL;

        #pragma unroll
        for (int q = 0; q < 32; q++) {
            #pragma unroll
            for (int r = 0; r < 4; r++) {
                ulonglong2 hv = ((const ulonglong2*)hbuf[cur][r])[q];
                acc[r] = ffma2(hv.x, wpk[2 * q],     acc[r]);
                acc[r] = ffma2(hv.y, wpk[2 * q + 1], acc[r]);
            }
        }

        const int nxt = cur ^ 1;
        #pragma unroll
        for (int r = 0; r < 4; r++) {
            float2 s = unpack2(acc[r]);
            hbuf[nxt][r][j] = fast_tanh(s.x + s.y + px[r]);
        }
        #pragma unroll
        for (int r = 0; r < 4; r++) idxA[r] = idxB[r];
        cur = nxt;
        __syncthreads();
    }

    #pragma unroll
    for (int r = 0; r < 4; r++)
        g_H[(b0 + r) * HID + j] = hbuf[cur][r][j];
}

// ============================================================================
// launch
// ============================================================================
extern "C" void kernel_launch(void* const* d_in, const int* in_sizes, int n_in,
                              void* d_out, int out_size) {
    const int*   x    = (const int*)d_in[0];     // int32: JAX downcasts int64
    const float* emb  = (const float*)d_in[1];
    const float* W_ih = (const float*)d_in[2];
    const float* W_hh = (const float*)d_in[3];
    const float* b_ih = (const float*)d_in[4];
    const float* b_hh = (const float*)d_in[5];
    const float* W_fc = (const float*)d_in[6];
    const float* b_fc = (const float*)d_in[7];
    float*       out  = (float*)d_out;

    static float* g_P_ptr = nullptr;
    static float* g_H_ptr = nullptr;
    if (!g_P_ptr) { cudaGetSymbolAddress((void**)&g_P_ptr, g_P);
                    cudaGetSymbolAddress((void**)&g_H_ptr, g_H); }

    const int smem = 4 * TILE_B;  // 131072
    cudaFuncSetAttribute(k_gemm_mma, cudaFuncAttributeMaxDynamicSharedMemorySize, smem);

    // A: P[v][j] = emb[v]·W_ih[j] + (b_ih+b_hh)[j].  M=v (emb), N=j (W_ih), K=100
    k_gemm_mma<<<dim3(VOCAB / 128, 1), 256, smem>>>(
        emb, EMBED, W_ih, EMBED, EMBED, g_P_ptr, HID, b_ih, b_hh);

    // B: recurrent scan
    k_rnn_scan<<<BATCH / 4, 128>>>(x, W_hh);

    // C: out[b][v] = h[b]·W_fc[v] + b_fc[v].  M=b (h), N=v (W_fc), K=128
    k_gemm_mma<<<dim3(BATCH / 128, VOCAB / 128), 256, smem>>>(
        g_H_ptr, HID, W_fc, HID, HID, out, VOCAB, b_fc, nullptr);
}

// round 7
// speedup vs baseline: 2.0947x; 1.1973x over previous
#include <cuda_runtime.h>
#include <cuda_bf16.h>
#include <cstdint>

// Problem constants
#define VOCAB  32000
#define EMBED  100
#define HID    128
#define BATCH  1024
#define SEQ    256

// -------- device scratch (no allocation allowed) --------
__device__ __align__(16) float g_P[VOCAB * HID];            // fused projections (16.4 MB)
__device__ __align__(16) __nv_bfloat16 g_Ehi[VOCAB * 128];  // emb split (padded K=128)
__device__ __align__(16) __nv_bfloat16 g_Elo[VOCAB * 128];
__device__ __align__(16) __nv_bfloat16 g_Whi[VOCAB * 128];  // W_fc split
__device__ __align__(16) __nv_bfloat16 g_Wlo[VOCAB * 128];
__device__ __align__(16) __nv_bfloat16 g_IHhi[128 * 128];   // W_ih split
__device__ __align__(16) __nv_bfloat16 g_IHlo[128 * 128];
__device__ __align__(16) __nv_bfloat16 g_Hhi[BATCH * 128];  // h_last split
__device__ __align__(16) __nv_bfloat16 g_Hlo[BATCH * 128];

// ============================================================================
// Pre-split conversion: fp32 [rows][Kv] -> hi/lo bf16 [rows][128] (zero-pad).
// One warp per row; each lane covers TWO column-pairs (cp = lane, lane+32) so
// the full 128 columns are written (round-6 bug: only cols 0..63 were).
// ============================================================================
__global__ void __launch_bounds__(256) k_cvt(
    const float* __restrict__ src, int Kv,
    __nv_bfloat16* __restrict__ hi, __nv_bfloat16* __restrict__ lo)
{
    const int r    = blockIdx.x * 8 + (threadIdx.x >> 5);
    const int lane = threadIdx.x & 31;
    #pragma unroll
    for (int cp = lane; cp < 64; cp += 32) {
        const int c0 = 2 * cp;
        float a = (c0     < Kv) ? src[(long long)r * Kv + c0]     : 0.0f;
        float b = (c0 + 1 < Kv) ? src[(long long)r * Kv + c0 + 1] : 0.0f;
        __nv_bfloat16 ha = __float2bfloat16_rn(a), hb = __float2bfloat16_rn(b);
        __nv_bfloat16 la = __float2bfloat16_rn(a - __bfloat162float(ha));
        __nv_bfloat16 lb = __float2bfloat16_rn(b - __bfloat162float(hb));
        ((uint32_t*)hi)[r * 64 + cp] = (uint32_t)*(uint16_t*)&ha | ((uint32_t)*(uint16_t*)&hb << 16);
        ((uint32_t*)lo)[r * 64 + cp] = (uint32_t)*(uint16_t*)&la | ((uint32_t)*(uint16_t*)&lb << 16);
    }
}

// ============================================================================
// mma.sync bf16 GEMM (plain PTX ISA; tcgen05 unavailable on base sm_100 target)
// D = Ahi*Bhi + Ahi*Blo + Alo*Bhi, fp32 accum (~2^-18 operand error).
// Block tile 128M x 64N, K=128 single-shot. 8 warps = 4M x 2N of 32x32.
// smem 96KB -> 2 CTAs/SM (prologue of one overlaps MMA of the other).
// ============================================================================
__device__ __forceinline__ uint32_t smem_u32(const void* p) {
    uint32_t a;
    asm("{ .reg .u64 t; cvta.to.shared.u64 t, %1; cvt.u32.u64 %0, t; }" : "=r"(a) : "l"(p));
    return a;
}
__device__ __forceinline__ void ldmx4(uint32_t* r, uint32_t a) {
    asm volatile("ldmatrix.sync.aligned.m8n8.x4.shared.b16 {%0,%1,%2,%3}, [%4];"
                 : "=r"(r[0]), "=r"(r[1]), "=r"(r[2]), "=r"(r[3]) : "r"(a));
}
__device__ __forceinline__ void mma_bf16(float* c, const uint32_t* a,
                                         uint32_t b0, uint32_t b1) {
    asm volatile("mma.sync.aligned.m16n8k16.row.col.f32.bf16.bf16.f32 "
                 "{%0,%1,%2,%3}, {%4,%5,%6,%7}, {%8,%9}, {%0,%1,%2,%3};"
                 : "+f"(c[0]), "+f"(c[1]), "+f"(c[2]), "+f"(c[3])
                 : "r"(a[0]), "r"(a[1]), "r"(a[2]), "r"(a[3]), "r"(b0), "r"(b1));
}
// swizzled tile layout: row stride 256B, 16B unit index u' = u ^ (row & 7)
__device__ __forceinline__ uint32_t tswz(int row, int u) {
    return (uint32_t)(row * 256 + ((u ^ (row & 7)) << 4));
}
#define A_TILE 32768
#define B_TILE 16384
#define GEMM_SMEM (2 * A_TILE + 2 * B_TILE)   // 98304

// copy bf16 [rows][128] global tile into swizzled smem (16B granules)
__device__ __forceinline__ void load_tile(const __nv_bfloat16* __restrict__ g,
                                          char* s, int rows, int tid) {
    #pragma unroll 4
    for (int i = tid; i < rows * 16; i += 256) {
        int row = i >> 4, u = i & 15;
        *(uint4*)(s + tswz(row, u)) = *(const uint4*)(g + (long long)row * 128 + u * 8);
    }
}

__global__ void __launch_bounds__(256, 2) k_gemm(
    const __nv_bfloat16* __restrict__ Ahi_g, const __nv_bfloat16* __restrict__ Alo_g,
    const __nv_bfloat16* __restrict__ Bhi_g, const __nv_bfloat16* __restrict__ Blo_g,
    float* __restrict__ out, long long ldout,
    const float* __restrict__ bias1, const float* __restrict__ bias2)
{
    extern __shared__ __align__(16) char sm[];
    __shared__ float sbias[64];
    char* Ahi = sm;
    char* Alo = sm + A_TILE;
    char* Bhi = sm + 2 * A_TILE;
    char* Blo = sm + 2 * A_TILE + B_TILE;

    const int tid = threadIdx.x, w = tid >> 5, lane = tid & 31;
    const int wm = w >> 1, wn = w & 1;
    const int m0 = blockIdx.x * 128, n0 = blockIdx.y * 64;

    load_tile(Ahi_g + (long long)m0 * 128, Ahi, 128, tid);
    load_tile(Alo_g + (long long)m0 * 128, Alo, 128, tid);
    load_tile(Bhi_g + (long long)n0 * 128, Bhi, 64, tid);
    load_tile(Blo_g + (long long)n0 * 128, Blo, 64, tid);
    if (tid < 64) sbias[tid] = bias1[n0 + tid] + (bias2 ? bias2[n0 + tid] : 0.0f);
    __syncthreads();

    const int sw = lane & 7;
    const int arow = wm * 32 + (lane & 15);
    const int akh  = lane >> 4;
    const int brow = wn * 32 + (lane & 7) + 8 * (lane >> 4);
    const int bkh  = (lane >> 3) & 1;

    const uint32_t sA0h = smem_u32(Ahi) + arow * 256;
    const uint32_t sA0l = smem_u32(Alo) + arow * 256;
    const uint32_t sB0h = smem_u32(Bhi) + brow * 256;
    const uint32_t sB0l = smem_u32(Blo) + brow * 256;

    float acc[2][4][4];
    #pragma unroll
    for (int mt = 0; mt < 2; mt++)
        #pragma unroll
        for (int nt = 0; nt < 4; nt++)
            #pragma unroll
            for (int q = 0; q < 4; q++) acc[mt][nt][q] = 0.0f;

    #pragma unroll
    for (int ks = 0; ks < 8; ks++) {
        const uint32_t uA = (uint32_t)(((2 * ks + akh) ^ sw) << 4);
        const uint32_t uB = (uint32_t)(((2 * ks + bkh) ^ sw) << 4);
        uint32_t aHi[2][4], aLo[2][4];
        ldmx4(aHi[0], sA0h + uA);
        ldmx4(aHi[1], sA0h + 16 * 256 + uA);
        ldmx4(aLo[0], sA0l + uA);
        ldmx4(aLo[1], sA0l + 16 * 256 + uA);
        #pragma unroll
        for (int np = 0; np < 2; np++) {
            uint32_t bh[4], bl[4];
            ldmx4(bh, sB0h + np * 16 * 256 + uB);
            ldmx4(bl, sB0l + np * 16 * 256 + uB);
            #pragma unroll
            for (int mt = 0; mt < 2; mt++) {
                mma_bf16(acc[mt][2 * np],     aHi[mt], bh[0], bh[1]);
                mma_bf16(acc[mt][2 * np + 1], aHi[mt], bh[2], bh[3]);
                mma_bf16(acc[mt][2 * np],     aLo[mt], bh[0], bh[1]);
                mma_bf16(acc[mt][2 * np + 1], aLo[mt], bh[2], bh[3]);
                mma_bf16(acc[mt][2 * np],     aHi[mt], bl[0], bl[1]);
                mma_bf16(acc[mt][2 * np + 1], aHi[mt], bl[2], bl[3]);
            }
        }
    }

    // epilogue: rows m0+wm*32+mt*16+g [+8], cols n0+wn*32+nt*8+2*tig
    const int g = lane >> 2, tig = lane & 3;
    #pragma unroll
    for (int mt = 0; mt < 2; mt++) {
        const long long r0 = (long long)(m0 + wm * 32 + mt * 16 + g) * ldout + n0;
        const long long r1 = r0 + 8 * ldout;
        #pragma unroll
        for (int nt = 0; nt < 4; nt++) {
            const int col = wn * 32 + nt * 8 + 2 * tig;
            const float bx = sbias[col], by = sbias[col + 1];
            *(float2*)(out + r0 + col) = make_float2(acc[mt][nt][0] + bx, acc[mt][nt][1] + by);
            *(float2*)(out + r1 + col) = make_float2(acc[mt][nt][2] + bx, acc[mt][nt][3] + by);
        }
    }
}

// ============================================================================
// Kernel B: RNN scan (unchanged core; epilogue emits hi/lo bf16 of h).
// ============================================================================
__device__ __forceinline__ unsigned long long ffma2(unsigned long long a,
                                                    unsigned long long b,
                                                    unsigned long long c) {
    unsigned long long d;
    asm("fma.rn.f32x2 %0, %1, %2, %3;" : "=l"(d) : "l"(a), "l"(b), "l"(c));
    return d;
}
__device__ __forceinline__ float2 unpack2(unsigned long long v) {
    float lo, hi;
    asm("mov.b64 {%0, %1}, %2;" : "=f"(lo), "=f"(hi) : "l"(v));
    return make_float2(lo, hi);
}
__device__ __forceinline__ float fast_tanh(float x) {
    float e = __expf(2.0f * x);
    return 1.0f - __fdividef(2.0f, e + 1.0f);
}

__global__ void __launch_bounds__(128, 2) k_rnn_scan(
    const int* __restrict__ x, const float* __restrict__ W_hh)
{
    __shared__ __align__(16) float hbuf[2][4][HID];
    const int j  = threadIdx.x;
    const int b0 = blockIdx.x * 4;

    unsigned long long wpk[64];
    const unsigned long long* Wr = (const unsigned long long*)W_hh + (long long)j * 64;
    #pragma unroll
    for (int q = 0; q < 64; q++) wpk[q] = Wr[q];

    #pragma unroll
    for (int r = 0; r < 4; r++) hbuf[0][r][j] = 0.0f;
    __syncthreads();

    int idxA[4];
    #pragma unroll
    for (int r = 0; r < 4; r++) idxA[r] = x[(b0 + r) * SEQ];

    int cur = 0;
    for (int t = 0; t < SEQ; t++) {
        int idxB[4];
        if (t < SEQ - 1) {
            #pragma unroll
            for (int r = 0; r < 4; r++) idxB[r] = x[(b0 + r) * SEQ + t + 1];
        } else {
            #pragma unroll
            for (int r = 0; r < 4; r++) idxB[r] = idxA[r];
        }
        float px[4];
        #pragma unroll
        for (int r = 0; r < 4; r++) px[r] = g_P[idxA[r] * HID + j];

        unsigned long long acc[4];
        #pragma unroll
        for (int r = 0; r < 4; r++) acc[r] = 0ULL;

        #pragma unroll
        for (int q = 0; q < 32; q++) {
            #pragma unroll
            for (int r = 0; r < 4; r++) {
                ulonglong2 hv = ((const ulonglong2*)hbuf[cur][r])[q];
                acc[r] = ffma2(hv.x, wpk[2 * q],     acc[r]);
                acc[r] = ffma2(hv.y, wpk[2 * q + 1], acc[r]);
            }
        }

        const int nxt = cur ^ 1;
        #pragma unroll
        for (int r = 0; r < 4; r++) {
            float2 s = unpack2(acc[r]);
            hbuf[nxt][r][j] = fast_tanh(s.x + s.y + px[r]);
        }
        #pragma unroll
        for (int r = 0; r < 4; r++) idxA[r] = idxB[r];
        cur = nxt;
        __syncthreads();
    }

    // epilogue: split h -> hi/lo bf16 packed pairs (threads 0..63 per row pair)
    if (j < 64) {
        #pragma unroll
        for (int r = 0; r < 4; r++) {
            float a = hbuf[cur][r][2 * j], b = hbuf[cur][r][2 * j + 1];
            __nv_bfloat16 ha = __float2bfloat16_rn(a), hb = __float2bfloat16_rn(b);
            __nv_bfloat16 la = __float2bfloat16_rn(a - __bfloat162float(ha));
            __nv_bfloat16 lb = __float2bfloat16_rn(b - __bfloat162float(hb));
            ((uint32_t*)g_Hhi)[(b0 + r) * 64 + j] =
                (uint32_t)*(uint16_t*)&ha | ((uint32_t)*(uint16_t*)&hb << 16);
            ((uint32_t*)g_Hlo)[(b0 + r) * 64 + j] =
                (uint32_t)*(uint16_t*)&la | ((uint32_t)*(uint16_t*)&lb << 16);
        }
    }
}

// ============================================================================
// launch
// ============================================================================
extern "C" void kernel_launch(void* const* d_in, const int* in_sizes, int n_in,
                              void* d_out, int out_size) {
    const int*   x    = (const int*)d_in[0];     // int32: JAX downcasts int64
    const float* emb  = (const float*)d_in[1];
    const float* W_ih = (const float*)d_in[2];
    const float* W_hh = (const float*)d_in[3];
    const float* b_ih = (const float*)d_in[4];
    const float* b_hh = (const float*)d_in[5];
    const float* W_fc = (const float*)d_in[6];
    const float* b_fc = (const float*)d_in[7];
    float*       out  = (float*)d_out;

    static float* P_p = nullptr;
    static __nv_bfloat16 *Ehi_p, *Elo_p, *Whi_p, *Wlo_p, *IHhi_p, *IHlo_p, *Hhi_p, *Hlo_p;
    if (!P_p) {
        cudaGetSymbolAddress((void**)&P_p,    g_P);
        cudaGetSymbolAddress((void**)&Ehi_p,  g_Ehi);
        cudaGetSymbolAddress((void**)&Elo_p,  g_Elo);
        cudaGetSymbolAddress((void**)&Whi_p,  g_Whi);
        cudaGetSymbolAddress((void**)&Wlo_p,  g_Wlo);
        cudaGetSymbolAddress((void**)&IHhi_p, g_IHhi);
        cudaGetSymbolAddress((void**)&IHlo_p, g_IHlo);
        cudaGetSymbolAddress((void**)&Hhi_p,  g_Hhi);
        cudaGetSymbolAddress((void**)&Hlo_p,  g_Hlo);
        cudaFuncSetAttribute(k_gemm, cudaFuncAttributeMaxDynamicSharedMemorySize, GEMM_SMEM);
    }

    // pre-split weights/embeddings to hi/lo bf16 (K padded to 128)
    k_cvt<<<VOCAB / 8, 256>>>(emb,  EMBED, Ehi_p,  Elo_p);
    k_cvt<<<HID / 8,   256>>>(W_ih, EMBED, IHhi_p, IHlo_p);
    k_cvt<<<VOCAB / 8, 256>>>(W_fc, HID,   Whi_p,  Wlo_p);

    // P[v][j] = emb[v]·W_ih[j] + (b_ih+b_hh)[j]
    k_gemm<<<dim3(VOCAB / 128, HID / 64), 256, GEMM_SMEM>>>(
        Ehi_p, Elo_p, IHhi_p, IHlo_p, P_p, HID, b_ih, b_hh);

    // recurrent scan (writes g_Hhi/g_Hlo)
    k_rnn_scan<<<BATCH / 4, 128>>>(x, W_hh);

    // out[b][v] = h[b]·W_fc[v] + b_fc[v]; x=batch so consecutive CTAs share W_fc tile in L2
    k_gemm<<<dim3(BATCH / 128, VOCAB / 64), 256, GEMM_SMEM>>>(
        Hhi_p, Hlo_p, Whi_p, Wlo_p, out, VOCAB, b_fc, nullptr);
}